// round 2
// baseline (speedup 1.0000x reference)
#include <cuda_runtime.h>
#include <cstdint>

// ---------------------------------------------------------------------------
// SinkhornDistance (degenerate loop): out[b] = sum_{i,j} c * exp(-c/0.1),
//   c = (xs_i - ys_j)^2 + (x_i - y_j)^2,  B=8, N=M=4096.
// MUFU.EX2-bound: 4.19M warp-exps -> ~56.6K cyc/SMSP floor (~26us).
// This round: single balanced wave (grid=592 persistent), scaled-cost trick
// (multiplier = K*c, rescale at end), packed accumulate.
// ---------------------------------------------------------------------------

#define PACK2(out, lo, hi)  asm("mov.b64 %0, {%1, %2};" : "=l"(out) : "f"(lo), "f"(hi))
#define UNPACK2(lo, hi, in) asm("mov.b64 {%0, %1}, %2;" : "=f"(lo), "=f"(hi) : "l"(in))
#define ADD2(out, a, b)     asm("add.rn.f32x2 %0, %1, %2;" : "=l"(out) : "l"(a), "l"(b))
#define MUL2(out, a, b)     asm("mul.rn.f32x2 %0, %1, %2;" : "=l"(out) : "l"(a), "l"(b))
#define FMA2(out, a, b, c)  asm("fma.rn.f32x2 %0, %1, %2, %3;" : "=l"(out) : "l"(a), "l"(b), "l"(c))

static __device__ __forceinline__ float ex2f(float v) {
    float r;
    asm("ex2.approx.ftz.f32 %0, %1;" : "=f"(r) : "f"(v));
    return r;
}

static constexpr int B_    = 8;
static constexpr int N_    = 4096;
static constexpr int M_    = 4096;
static constexpr int TPB   = 256;
static constexpr int JPT   = 16;            // columns per thread; TPB*JPT == M
static constexpr int ROWS  = 4;             // rows per tile
static constexpr int TILES_PER_B = N_ / ROWS;       // 1024
static constexpr int TILES = B_ * TILES_PER_B;      // 8192
static constexpr int GRID  = 592;           // 4 blocks per SM, one wave

// exp(-c/0.1) = exp2(c * K),  K = -10*log2(e)
static constexpr float NEG_K = -14.4269504088896341f;
// We accumulate S' = sum (K*c) * exp2(K*c) = K * S  ->  S = S' * (1/K) = S' * (-ln2/10)
static constexpr float INV_K = -0.06931471805599453f;

__global__ void __launch_bounds__(TPB, 4)
sinkhorn_kernel(const float* __restrict__ x,  const float* __restrict__ y,
                const float* __restrict__ xs, const float* __restrict__ ys,
                float* __restrict__ out)
{
    const int t   = threadIdx.x;
    const int jb  = t * JPT;
    const int bid = blockIdx.x;

    // Contiguous balanced range of tiles for this block
    const int lo = (int)(((long long)TILES * bid)       / GRID);
    const int hi = (int)(((long long)TILES * (bid + 1)) / GRID);

    unsigned long long ny[JPT / 2], nys[JPT / 2];
    unsigned long long K2;
    PACK2(K2, NEG_K, NEG_K);

    __shared__ float wsum[TPB / 32];

    int cur_b = -1;
    unsigned long long acc2 = 0ull;   // packed {0.f, 0.f}

    for (int tile = lo; tile <= hi; tile++) {
        const int b = (tile < hi) ? (tile >> 10) : -2;   // tile / TILES_PER_B; -2 => final flush

        if (b != cur_b) {
            // Flush accumulated sum for previous batch (block-uniform path)
            if (cur_b >= 0) {
                float a0, a1;
                UNPACK2(a0, a1, acc2);
                float acc = a0 + a1;
#pragma unroll
                for (int off = 16; off > 0; off >>= 1)
                    acc += __shfl_xor_sync(0xffffffffu, acc, off);
                __syncthreads();                    // protect wsum reuse
                if ((t & 31) == 0) wsum[t >> 5] = acc;
                __syncthreads();
                if (t < TPB / 32) {
                    float v = wsum[t];
#pragma unroll
                    for (int off = TPB / 64; off > 0; off >>= 1)
                        v += __shfl_xor_sync(0x000000ffu, v, off);
                    if (t == 0) atomicAdd(out + cur_b, v * INV_K);
                }
                acc2 = 0ull;
            }
            if (b < 0) break;                       // done
            // Load this thread's 16 (y, ys) columns for the new batch, negated+packed
            const float4* y4  = reinterpret_cast<const float4*>(y  + (size_t)b * M_ + jb);
            const float4* ys4 = reinterpret_cast<const float4*>(ys + (size_t)b * M_ + jb);
#pragma unroll
            for (int q = 0; q < JPT / 4; q++) {
                float4 a = y4[q];
                float4 s = ys4[q];
                PACK2(ny[2 * q],      -a.x, -a.y);
                PACK2(ny[2 * q + 1],  -a.z, -a.w);
                PACK2(nys[2 * q],     -s.x, -s.y);
                PACK2(nys[2 * q + 1], -s.z, -s.w);
            }
            cur_b = b;
        }

        const int i0 = (tile & (TILES_PER_B - 1)) * ROWS;
        const float* xrow  = x  + (size_t)cur_b * N_ + i0;
        const float* xsrow = xs + (size_t)cur_b * N_ + i0;

#pragma unroll
        for (int r = 0; r < ROWS; r++) {
            const float xi  = __ldg(xrow + r);      // uniform -> L1 broadcast
            const float xsi = __ldg(xsrow + r);
            unsigned long long xi2, xsi2;
            PACK2(xi2,  xi,  xi);
            PACK2(xsi2, xsi, xsi);

#pragma unroll
            for (int k = 0; k < JPT / 2; k++) {
                unsigned long long d1, d2, sq, c, tt, e2;
                ADD2(d1, xsi2, nys[k]);             // xs_i - ys_j   (x2)
                ADD2(d2, xi2,  ny[k]);              // x_i  - y_j    (x2)
                MUL2(sq, d1, d1);
                FMA2(c,  d2, d2, sq);               // cost
                MUL2(tt, c,  K2);                   // K * cost  (<= 0)
                float t0, t1;
                UNPACK2(t0, t1, tt);
                float e0 = ex2f(t0);
                float e1 = ex2f(t1);
                PACK2(e2, e0, e1);
                FMA2(acc2, tt, e2, acc2);           // += (K*c) * exp2(K*c)
            }
        }
    }
}

__global__ void zero_kernel(float* out, int n) {
    int i = blockIdx.x * blockDim.x + threadIdx.x;
    if (i < n) out[i] = 0.0f;
}

extern "C" void kernel_launch(void* const* d_in, const int* in_sizes, int n_in,
                              void* d_out, int out_size)
{
    const float* x  = (const float*)d_in[0];
    const float* y  = (const float*)d_in[1];
    const float* xs = (const float*)d_in[2];
    const float* ys = (const float*)d_in[3];
    float* out = (float*)d_out;

    (void)in_sizes; (void)n_in;

    zero_kernel<<<1, 32>>>(out, out_size);
    sinkhorn_kernel<<<GRID, TPB>>>(x, y, xs, ys, out);
}

// round 3
// speedup vs baseline: 1.9958x; 1.9958x over previous
#include <cuda_runtime.h>

// ---------------------------------------------------------------------------
// SinkhornDistance (degenerate loop):
//   out[b] = sum_{i,j} g(xs_i - ys_j, x_i - y_j),
//   g(d1,d2) = c * exp(-10c), c = d1^2 + d2^2.
// Separable: g = s(d1)k(d2) + k(d1)s(d2), k(t)=e^{-10t^2}, s(t)=t^2 e^{-10t^2}.
// Chebyshev tensor interpolation (n=32/dim) =>
//   out[b] = <S, Wx K Wy^T> + <K, Wx S Wy^T>
// with Wx[a,b] = sum_i L_a(xs_i) L_b(x_i), Wy likewise for (ys, y).
// Replaces 134M exps (MUFU floor ~33us) with 67M FMAs (~4us).
// ---------------------------------------------------------------------------

#define NCH 32
#define NPTS 4096
#define NBATCH 8

__device__ float g_P [NCH];              // Chebyshev nodes cos((2a+1)pi/64)
__device__ float g_Wt[NCH];              // barycentric weights (-1)^a sin((2a+1)pi/64)
__device__ float g_K [NCH * NCH];        // k((p_a - p_c)/2)
__device__ float g_S [NCH * NCH];        // s((p_a - p_c)/2)
__device__ float g_W [NBATCH * 2 * NCH * NCH];   // moment matrices (atomically built)

// ---- setup: nodes, weights, kernel matrices, zero the moment scratch ------
__global__ void k_setup() {
    int t = threadIdx.x;                 // 1024 threads
    if (t < NCH) {
        float u = (2.0f * t + 1.0f) / (2.0f * NCH);
        g_P[t] = cospif(u);
        float s = sinpif(u);
        g_Wt[t] = (t & 1) ? -s : s;
    }
    int a = t >> 5, c = t & 31;
    float pa = cospif((2.0f * a + 1.0f) / (2.0f * NCH));
    float pc = cospif((2.0f * c + 1.0f) / (2.0f * NCH));
    float d  = 0.5f * (pa - pc);         // node diff in original coords
    float c2 = d * d;
    float e  = expf(-10.0f * c2);
    g_K[t] = e;
    g_S[t] = c2 * e;
    for (int i = t; i < NBATCH * 2 * NCH * NCH; i += 1024) g_W[i] = 0.0f;
}

// ---- moment GEMM: Wx/Wy[a,b] = sum over a 128-point chunk -----------------
// grid = 8 batches * 2 sides * 32 chunks = 512 blocks, 64 threads each.
__global__ void __launch_bounds__(64) k_moments(
    const float* __restrict__ x,  const float* __restrict__ y,
    const float* __restrict__ xs, const float* __restrict__ ys)
{
    const int blk   = blockIdx.x;
    const int chunk = blk & 31;
    const int side  = (blk >> 5) & 1;
    const int batch = blk >> 6;
    const float* A  = side ? ys : xs;    // support coordinate -> basis index a
    const float* Bv = side ? y  : x;     // value coordinate   -> basis index b
    const int base  = batch * NPTS + chunk * 128;

    __shared__ float sp[NCH], sw[NCH];
    __shared__ float bas[2][128][NCH + 1];

    const int tid = threadIdx.x;
    if (tid < NCH) { sp[tid] = g_P[tid]; sw[tid] = g_Wt[tid]; }
    __syncthreads();

    // Barycentric Lagrange basis for 128 points x 2 coords (256 tasks)
    for (int k = tid; k < 256; k += 64) {
        int pt = k & 127, which = k >> 7;
        float v  = which ? Bv[base + pt] : A[base + pt];
        float xi = 2.0f * v - 1.0f;                      // map [0,1] -> [-1,1]
        float tv[NCH];
        float ssum = 0.0f;
#pragma unroll
        for (int a = 0; a < NCH; a++) {
            float dd = xi - sp[a];
            dd = copysignf(fmaxf(fabsf(dd), 1e-12f), dd);  // near-node guard
            float q = __fdividef(sw[a], dd);
            tv[a] = q;
            ssum += q;
        }
        float inv = __fdividef(1.0f, ssum);
#pragma unroll
        for (int a = 0; a < NCH; a++) bas[which][pt][a] = tv[a] * inv;
    }
    __syncthreads();

    // 32x32 outer-product accumulation, 8x8 threads, 4x4 register tiles
    const int ty = tid >> 3, tx = tid & 7;
    float acc[4][4] = {};
#pragma unroll 2
    for (int i = 0; i < 128; i++) {
        float av[4], bv2[4];
#pragma unroll
        for (int r = 0; r < 4; r++) {
            av[r]  = bas[0][i][ty * 4 + r];
            bv2[r] = bas[1][i][tx * 4 + r];
        }
#pragma unroll
        for (int r = 0; r < 4; r++)
#pragma unroll
            for (int c = 0; c < 4; c++)
                acc[r][c] = fmaf(av[r], bv2[c], acc[r][c]);
    }

    float* Wp = g_W + (batch * 2 + side) * NCH * NCH;
#pragma unroll
    for (int r = 0; r < 4; r++)
#pragma unroll
        for (int c = 0; c < 4; c++)
            atomicAdd(&Wp[(ty * 4 + r) * NCH + (tx * 4 + c)], acc[r][c]);
}

// ---- final contraction: out[b] = <S, Wx K Wy^T> + <K, Wx S Wy^T> ----------
// grid = 8 (one block per batch), 1024 threads.
__global__ void __launch_bounds__(1024) k_final(float* __restrict__ out)
{
    const int b = blockIdx.x, t = threadIdx.x;
    const int PI = NCH + 1;                       // smem pitch 33 (bank-safe)
    __shared__ float sWx[NCH * PI], sWy[NCH * PI];
    __shared__ float sK [NCH * PI], sS [NCH * PI];
    __shared__ float sP [NCH * PI], sQ [NCH * PI];
    __shared__ float red[32];

    const int a = t >> 5, d = t & 31;
    sWx[a * PI + d] = g_W[(b * 2 + 0) * NCH * NCH + t];
    sWy[a * PI + d] = g_W[(b * 2 + 1) * NCH * NCH + t];
    sK [a * PI + d] = g_K[t];
    sS [a * PI + d] = g_S[t];
    __syncthreads();

    // P = Wx*K, Q = Wx*S   (thread = (a,d))
    float p = 0.0f, q = 0.0f;
#pragma unroll
    for (int bb = 0; bb < NCH; bb++) {
        float w = sWx[a * PI + bb];
        p = fmaf(w, sK[bb * PI + d], p);
        q = fmaf(w, sS[bb * PI + d], q);
    }
    sP[a * PI + d] = p;
    sQ[a * PI + d] = q;
    __syncthreads();

    // M = P*Wy^T, N = Q*Wy^T; part = S.*M + K.*N   (thread = (a,c))
    const int c = d;
    float m = 0.0f, n = 0.0f;
#pragma unroll
    for (int dd = 0; dd < NCH; dd++) {
        float wy = sWy[c * PI + dd];
        m = fmaf(sP[a * PI + dd], wy, m);
        n = fmaf(sQ[a * PI + dd], wy, n);
    }
    float part = sS[a * PI + c] * m + sK[a * PI + c] * n;

    // block reduction (32 warps)
#pragma unroll
    for (int off = 16; off > 0; off >>= 1)
        part += __shfl_xor_sync(0xffffffffu, part, off);
    if ((t & 31) == 0) red[t >> 5] = part;
    __syncthreads();
    if (t < 32) {
        float v = red[t];
#pragma unroll
        for (int off = 16; off > 0; off >>= 1)
            v += __shfl_xor_sync(0xffffffffu, v, off);
        if (t == 0) out[b] = v;
    }
}

extern "C" void kernel_launch(void* const* d_in, const int* in_sizes, int n_in,
                              void* d_out, int out_size)
{
    const float* x  = (const float*)d_in[0];
    const float* y  = (const float*)d_in[1];
    const float* xs = (const float*)d_in[2];
    const float* ys = (const float*)d_in[3];
    float* out = (float*)d_out;
    (void)in_sizes; (void)n_in; (void)out_size;

    k_setup  <<<1, 1024>>>();
    k_moments<<<512, 64>>>(x, y, xs, ys);
    k_final  <<<NBATCH, 1024>>>(out);
}

// round 4
// speedup vs baseline: 2.1072x; 1.0558x over previous
#include <cuda_runtime.h>

// ---------------------------------------------------------------------------
// SinkhornDistance (degenerate loop):
//   out[b] = sum_{i,j} g(xs_i - ys_j, x_i - y_j), g(d1,d2)=c*exp(-10c),
//   c = d1^2 + d2^2.  Separable rank-2 => Chebyshev tensor algebra:
//   out[b] = <S, Wx K Wy^T> + <K, Wx S Wy^T>,
//   Wx[a,b] = sum_i L_a(xs_i) L_b(x_i)   (n=32 first-kind nodes).
// R4: two kernels only (setup fused), packed-f32x2 broadcast moment GEMM.
// ---------------------------------------------------------------------------

#define NCH   32
#define NPTS  4096
#define NB    8
#define CHUNK 256                       // points per moments block
#define NCHUNK (NPTS / CHUNK)           // 16
#define MOM_GRID (NB * 2 * NCHUNK)      // 256
#define MOM_TPB  128                    // 4 warps, 64 pts each
#define PPW   64

#define PACK2(out, lo, hi)  asm("mov.b64 %0, {%1, %2};" : "=l"(out) : "f"(lo), "f"(hi))
#define UNPACK2(lo, hi, in) asm("mov.b64 {%0, %1}, %2;" : "=f"(lo), "=f"(hi) : "l"(in))
#define FMA2(out, a, b, c)  asm("fma.rn.f32x2 %0, %1, %2, %3;" : "=l"(out) : "l"(a), "l"(b), "l"(c))

// Moment matrices, layout [batch*2+side][a*32 + c]; zero-initialized, and
// k_final re-zeroes after consuming => invariant across graph replays.
__device__ float g_W[NB * 2 * NCH * NCH];

// ---- kernel 1: moments -----------------------------------------------------
__global__ void __launch_bounds__(MOM_TPB) k_moments(
    const float* __restrict__ x,  const float* __restrict__ y,
    const float* __restrict__ xs, const float* __restrict__ ys)
{
    __shared__ __align__(16) float sA[CHUNK * NCH];        // [pt][a], pitch 32
    __shared__ float sB[CHUNK * (NCH + 1)];                // [pt][c], pitch 33
    __shared__ float snode[NCH], swt[NCH];

    const int tid   = threadIdx.x;
    const int blk   = blockIdx.x;
    const int chunk = blk & (NCHUNK - 1);
    const int side  = (blk >> 4) & 1;
    const int batch = blk >> 5;

    if (tid < NCH) {
        float u = (2.0f * tid + 1.0f) / (2.0f * NCH);
        snode[tid] = cospif(u);
        float s = sinpif(u);
        swt[tid] = (tid & 1) ? -s : s;
    }
    __syncthreads();

    const float* A  = side ? ys : xs;   // support coord -> basis index a
    const float* Bv = side ? y  : x;    // value coord   -> basis index c
    const int base  = batch * NPTS + chunk * CHUNK;

    // Barycentric Lagrange basis: 512 tasks (256 pts x 2 coords)
    for (int k = tid; k < 2 * CHUNK; k += MOM_TPB) {
        const int pt = k & (CHUNK - 1);
        const int which = k >> 8;
        float v  = which ? Bv[base + pt] : A[base + pt];
        float xi = 2.0f * v - 1.0f;
        float tv[NCH];
        float ssum = 0.0f;
#pragma unroll
        for (int a = 0; a < NCH; a++) {
            float dd = xi - snode[a];
            dd = copysignf(fmaxf(fabsf(dd), 1e-12f), dd);
            float q = __fdividef(swt[a], dd);
            tv[a] = q;
            ssum += q;
        }
        float inv = __fdividef(1.0f, ssum);
        if (which) {
#pragma unroll
            for (int a = 0; a < NCH; a++) sB[pt * (NCH + 1) + a] = tv[a] * inv;
        } else {
#pragma unroll
            for (int a = 0; a < NCH; a++) sA[pt * NCH + a] = tv[a] * inv;
        }
    }
    __syncthreads();

    // Accumulate: warp owns all 32 columns (thread = column), rows packed x2.
    const int w    = tid >> 5;
    const int lane = tid & 31;
    const int p0   = w * PPW;

    unsigned long long acc[NCH / 2];
#pragma unroll
    for (int a2 = 0; a2 < NCH / 2; a2++) acc[a2] = 0ull;

    for (int i = 0; i < PPW; i++) {
        const int pt = p0 + i;
        float bv = sB[pt * (NCH + 1) + lane];          // coalesced
        unsigned long long bv2;
        PACK2(bv2, bv, bv);
        const unsigned long long* arow =
            reinterpret_cast<const unsigned long long*>(sA + pt * NCH);
#pragma unroll
        for (int a2 = 0; a2 < NCH / 2; a2++) {
            unsigned long long av = arow[a2];          // LDS.64 broadcast
            FMA2(acc[a2], av, bv2, acc[a2]);
        }
    }

    // Cross-warp reduce in smem (overlay on sA), then global atomics.
    __syncthreads();
    float* red = sA;                                   // 4*1024 floats <= 8192
#pragma unroll
    for (int a2 = 0; a2 < NCH / 2; a2++) {
        float lo, hi;
        UNPACK2(lo, hi, acc[a2]);
        red[w * 1024 + (2 * a2)     * NCH + lane] = lo;   // conflict-free
        red[w * 1024 + (2 * a2 + 1) * NCH + lane] = hi;
    }
    __syncthreads();

    float* Wp = g_W + (batch * 2 + side) * NCH * NCH;
#pragma unroll
    for (int k = 0; k < 8; k++) {
        int o = tid * 8 + k;                           // o = a*32 + c
        float v = red[o] + red[1024 + o] + red[2048 + o] + red[3072 + o];
        atomicAdd(&Wp[o], v);
    }
}

// ---- kernel 2: contraction + output + g_W re-zero --------------------------
__global__ void __launch_bounds__(1024) k_final(float* __restrict__ out)
{
    const int b = blockIdx.x, t = threadIdx.x;
    const int PI = NCH + 1;
    __shared__ float sWx[NCH * PI], sWy[NCH * PI];
    __shared__ float sK [NCH * PI], sS [NCH * PI];
    __shared__ float sP [NCH * PI], sQ [NCH * PI];
    __shared__ float red[32];

    const int a = t >> 5, d = t & 31;

    // Kernel matrices in-block (nodes bitwise-identical to k_moments')
    {
        float pa = cospif((2.0f * a + 1.0f) / (2.0f * NCH));
        float pc = cospif((2.0f * d + 1.0f) / (2.0f * NCH));
        float dd = 0.5f * (pa - pc);
        float c2 = dd * dd;
        float e  = expf(-10.0f * c2);
        sK[a * PI + d] = e;
        sS[a * PI + d] = c2 * e;
    }
    sWx[a * PI + d] = g_W[(b * 2 + 0) * NCH * NCH + t];   // coalesced
    sWy[a * PI + d] = g_W[(b * 2 + 1) * NCH * NCH + t];
    __syncthreads();

    // Re-zero moment scratch for the next graph replay.
    g_W[(b * 2 + 0) * NCH * NCH + t] = 0.0f;
    g_W[(b * 2 + 1) * NCH * NCH + t] = 0.0f;

    // P = Wx*K, Q = Wx*S
    float p = 0.0f, q = 0.0f;
#pragma unroll
    for (int bb = 0; bb < NCH; bb++) {
        float wv = sWx[a * PI + bb];
        p = fmaf(wv, sK[bb * PI + d], p);
        q = fmaf(wv, sS[bb * PI + d], q);
    }
    sP[a * PI + d] = p;
    sQ[a * PI + d] = q;
    __syncthreads();

    // part = S.*(P*Wy^T) + K.*(Q*Wy^T) at (a, c=d)
    float m = 0.0f, n = 0.0f;
#pragma unroll
    for (int dd = 0; dd < NCH; dd++) {
        float wy = sWy[d * PI + dd];
        m = fmaf(sP[a * PI + dd], wy, m);
        n = fmaf(sQ[a * PI + dd], wy, n);
    }
    float part = sS[a * PI + d] * m + sK[a * PI + d] * n;

#pragma unroll
    for (int off = 16; off > 0; off >>= 1)
        part += __shfl_xor_sync(0xffffffffu, part, off);
    if ((t & 31) == 0) red[t >> 5] = part;
    __syncthreads();
    if (t < 32) {
        float v = red[t];
#pragma unroll
        for (int off = 16; off > 0; off >>= 1)
            v += __shfl_xor_sync(0xffffffffu, v, off);
        if (t == 0) out[b] = v;
    }
}

extern "C" void kernel_launch(void* const* d_in, const int* in_sizes, int n_in,
                              void* d_out, int out_size)
{
    const float* x  = (const float*)d_in[0];
    const float* y  = (const float*)d_in[1];
    const float* xs = (const float*)d_in[2];
    const float* ys = (const float*)d_in[3];
    float* out = (float*)d_out;
    (void)in_sizes; (void)n_in; (void)out_size;

    k_moments<<<MOM_GRID, MOM_TPB>>>(x, y, xs, ys);
    k_final  <<<NB, 1024>>>(out);
}